// round 15
// baseline (speedup 1.0000x reference)
#include <cuda_runtime.h>
#include <cuda_fp16.h>
#include <cstdint>
#include <math.h>

#define T_TOK 8192
#define H_DIM 1024
#define I_DIM 4096
#define E_NUM 8
#define TOPK  2
#define CAP   17408       // 16384 pairs + worst-case alignment padding, mult of 128
#define BM 128
#define BN 128
#define BK 64             // 64 halves = 128B rows for A tile
#define NSTG 2
#define DSMEM_BYTES (1024 + NSTG * (BM * BK * 2 + BK * BN * 2))   // ~65 KB -> 2 CTAs/SM

// ---------------- scratch (device globals: allocation-free) ----------------
__device__ __half hs_h[(size_t)T_TOK * H_DIM];
__device__ __half gw_h[(size_t)E_NUM * H_DIM * I_DIM];
__device__ __half uw_h[(size_t)E_NUM * H_DIM * I_DIM];
__device__ __half dw_h[(size_t)E_NUM * I_DIM * H_DIM];
__device__ __half g_buf[(size_t)CAP * I_DIM];   // gate acts -> swiglu result in place
__device__ __half u_buf[(size_t)CAP * I_DIM];   // up acts
__device__ float d_buf[(size_t)CAP * H_DIM];    // per-slot down results (pre-combine)
__device__ int   pr_token[CAP];
__device__ float pr_weight[CAP];
__device__ int   slot_of[T_TOK * TOPK];         // token,k -> compacted slot row
__device__ int   tok_e[T_TOK * TOPK];
__device__ float tok_w[T_TOK * TOPK];
__device__ int   e_count[E_NUM];
__device__ int   e_cursor[E_NUM];
__device__ int   seg_off[E_NUM + 1];

// ---------------- ptx helpers (family-portable: sm_80/90 era) ----------------
__device__ __forceinline__ uint32_t smem_u32(const void* p) {
    uint32_t a;
    asm("{ .reg .u64 t; cvta.to.shared.u64 t, %1; cvt.u32.u64 %0, t; }" : "=r"(a) : "l"(p));
    return a;
}
__device__ __forceinline__ void cp16(uint32_t s, const void* g) {
    asm volatile("cp.async.cg.shared.global [%0], [%1], 16;" :: "r"(s), "l"(g));
}
__device__ __forceinline__ void cp_commit() {
    asm volatile("cp.async.commit_group;" ::: "memory");
}
template <int N>
__device__ __forceinline__ void cp_wait() {
    asm volatile("cp.async.wait_group %0;" :: "n"(N) : "memory");
}
__device__ __forceinline__ void ldm_x4(uint32_t* r, uint32_t a) {
    asm volatile("ldmatrix.sync.aligned.m8n8.x4.shared.b16 {%0,%1,%2,%3},[%4];"
                 : "=r"(r[0]), "=r"(r[1]), "=r"(r[2]), "=r"(r[3]) : "r"(a));
}
__device__ __forceinline__ void ldm_x4t(uint32_t* r, uint32_t a) {
    asm volatile("ldmatrix.sync.aligned.m8n8.x4.trans.shared.b16 {%0,%1,%2,%3},[%4];"
                 : "=r"(r[0]), "=r"(r[1]), "=r"(r[2]), "=r"(r[3]) : "r"(a));
}
__device__ __forceinline__ void mma16816(float* c, const uint32_t* a, const uint32_t* b) {
    asm volatile(
        "mma.sync.aligned.m16n8k16.row.col.f32.f16.f16.f32 "
        "{%0,%1,%2,%3},{%4,%5,%6,%7},{%8,%9},{%0,%1,%2,%3};"
        : "+f"(c[0]), "+f"(c[1]), "+f"(c[2]), "+f"(c[3])
        : "r"(a[0]), "r"(a[1]), "r"(a[2]), "r"(a[3]), "r"(b[0]), "r"(b[1]));
}

// ---------------- K0: init control state ----------------
__global__ void init_kernel() {
    int idx = blockIdx.x * blockDim.x + threadIdx.x;
    if (idx < E_NUM) { e_count[idx] = 0; e_cursor[idx] = 0; }
    if (idx < CAP)   { pr_token[idx] = 0; pr_weight[idx] = 0.f; }
}

// ---------------- f32 -> f16 conversion for weights (z selects tensor) ------
__global__ void cvt_w_kernel(const float* __restrict__ gw,
                             const float* __restrict__ uw,
                             const float* __restrict__ dw) {
    size_t i = ((size_t)blockIdx.x * blockDim.x + threadIdx.x) * 8;
    const float* src = (blockIdx.y == 0) ? gw : (blockIdx.y == 1) ? uw : dw;
    __half* dst = (blockIdx.y == 0) ? gw_h : (blockIdx.y == 1) ? uw_h : dw_h;
    float4 a = *(const float4*)(src + i);
    float4 b = *(const float4*)(src + i + 4);
    __half2 h[4] = { __floats2half2_rn(a.x, a.y), __floats2half2_rn(a.z, a.w),
                     __floats2half2_rn(b.x, b.y), __floats2half2_rn(b.z, b.w) };
    *(uint4*)(dst + i) = *(uint4*)h;
}

// ---------------- K1: router (1 warp per token, float4 loads) ---------------
// Side effect: converts hs -> hs_h (this kernel already streams all of hs).
__global__ void router_kernel(const float* __restrict__ hs,
                              const float* __restrict__ gpw) {
    __shared__ int s_cnt[E_NUM];
    int tid = threadIdx.x, warp = tid >> 5, lane = tid & 31;
    if (tid < E_NUM) s_cnt[tid] = 0;
    __syncthreads();

    int t = blockIdx.x * 8 + warp;
    const float* x = hs + (size_t)t * H_DIM;
    float acc[E_NUM];
#pragma unroll
    for (int e = 0; e < E_NUM; e++) acc[e] = 0.f;

#pragma unroll
    for (int it = 0; it < H_DIM / 128; it++) {          // 8 iters, 128 floats/warp/iter
        int kk = it * 128 + lane * 4;
        float4 xv = *(const float4*)(x + kk);
        __half2 h01 = __floats2half2_rn(xv.x, xv.y);
        __half2 h23 = __floats2half2_rn(xv.z, xv.w);
        uint2 hpk = make_uint2(*(uint32_t*)&h01, *(uint32_t*)&h23);
        *(uint2*)&hs_h[(size_t)t * H_DIM + kk] = hpk;
#pragma unroll
        for (int e = 0; e < E_NUM; e++) {
            float4 wv = *(const float4*)(gpw + e * H_DIM + kk);
            acc[e] = fmaf(xv.x, wv.x, acc[e]);
            acc[e] = fmaf(xv.y, wv.y, acc[e]);
            acc[e] = fmaf(xv.z, wv.z, acc[e]);
            acc[e] = fmaf(xv.w, wv.w, acc[e]);
        }
    }
#pragma unroll
    for (int e = 0; e < E_NUM; e++)
#pragma unroll
        for (int off = 16; off > 0; off >>= 1)
            acc[e] += __shfl_xor_sync(0xFFFFFFFFu, acc[e], off);

    if (lane == 0) {
        float m = acc[0];
#pragma unroll
        for (int e = 1; e < E_NUM; e++) m = fmaxf(m, acc[e]);
        int i0 = 0;
#pragma unroll
        for (int e = 1; e < E_NUM; e++) if (acc[e] > acc[i0]) i0 = e;
        int i1 = (i0 == 0) ? 1 : 0;
#pragma unroll
        for (int e = 0; e < E_NUM; e++)
            if (e != i0 && acc[e] > acc[i1]) i1 = e;
        float p0 = expf(acc[i0] - m);
        float p1 = expf(acc[i1] - m);
        float inv = 1.f / (p0 + p1);
        tok_e[2 * t]     = i0; tok_w[2 * t]     = p0 * inv;
        tok_e[2 * t + 1] = i1; tok_w[2 * t + 1] = p1 * inv;
        atomicAdd(&s_cnt[i0], 1);
        atomicAdd(&s_cnt[i1], 1);
    }
    __syncthreads();
    if (tid < E_NUM) atomicAdd(&e_count[tid], s_cnt[tid]);
}

// ---------------- K3: scatter (computes 128-aligned seg offsets in-block) ----
__global__ void scatter_kernel() {
    __shared__ int cnt[E_NUM];
    __shared__ int base[E_NUM];
    __shared__ int seg[E_NUM + 1];
    int tid = threadIdx.x;
    if (tid < E_NUM) cnt[tid] = 0;
    if (tid == 0) {
        int off = 0;
        for (int e = 0; e < E_NUM; e++) {
            seg[e] = off;
            off += (e_count[e] + BM - 1) & ~(BM - 1);
        }
        seg[E_NUM] = off;
        if (blockIdx.x == 0)
            for (int e = 0; e <= E_NUM; e++) seg_off[e] = seg[e];
    }
    __syncthreads();

    int t = blockIdx.x * 256 + tid;
    int e0 = tok_e[2 * t], e1 = tok_e[2 * t + 1];
    int r0 = atomicAdd(&cnt[e0], 1);
    int r1 = atomicAdd(&cnt[e1], 1);
    __syncthreads();
    if (tid < E_NUM) base[tid] = atomicAdd(&e_cursor[tid], cnt[tid]);
    __syncthreads();

    int p0 = seg[e0] + base[e0] + r0;
    pr_token[p0] = t; pr_weight[p0] = tok_w[2 * t];
    slot_of[2 * t] = p0;
    int p1 = seg[e1] + base[e1] + r1;
    pr_token[p1] = t; pr_weight[p1] = tok_w[2 * t + 1];
    slot_of[2 * t + 1] = p1;
}

// ---------------- grouped fp16 GEMM, BM=128/BN=128, 2 CTAs/SM ----------------
// B fragments register-double-buffered one ks ahead (LDSM latency hiding).
// GU: gate+up in one launch, z in {0,1} selects weight/dest. Grid m-fastest.
__global__ void __launch_bounds__(256, 2) moe_gemm_gu() {
    extern __shared__ char dsm[];
    const int KD = H_DIM, ND = I_DIM;

    int tid = threadIdx.x;
    int m0 = blockIdx.x * BM;
    int n0 = blockIdx.y * BN;
    int z  = blockIdx.z;               // 0 = gate, 1 = up
    if (m0 >= seg_off[E_NUM]) return;
    int e = 0;
    while (seg_off[e + 1] <= m0) ++e;

    uint32_t raw = smem_u32(dsm);
    uint32_t sbase = (raw + 1023u) & ~1023u;
    const uint32_t ASZ = BM * BK * 2;        // 16 KB
    const uint32_t BSZ = BK * BN * 2;        // 16 KB
    uint32_t aB[NSTG], bB[NSTG];
#pragma unroll
    for (int s = 0; s < NSTG; s++) {
        aB[s] = sbase + s * (ASZ + BSZ);
        bB[s] = sbase + s * (ASZ + BSZ) + ASZ;
    }

    const __half* Bw = z ? uw_h : gw_h;
    const __half* Bp = Bw + (size_t)e * KD * ND + n0;

    uint32_t aSo[4];
    const __half* aBase[4];
#pragma unroll
    for (int i = 0; i < 4; i++) {
        int idx = tid + i * 256;
        int r = idx >> 3, kg = idx & 7;
        int arow = pr_token[m0 + r];
        aBase[i] = hs_h + (size_t)arow * KD + kg * 8;
        aSo[i] = (uint32_t)(r * 128 + ((kg * 16) ^ ((r & 7) << 4)));
    }
    uint32_t bGo[4], bSo[4];
#pragma unroll
    for (int j = 0; j < 4; j++) {
        int idx = tid + j * 256;
        int k = idx >> 4, ng = idx & 15;
        bGo[j] = (uint32_t)(k * ND + ng * 8);
        bSo[j] = (uint32_t)(k * 256 + ((ng * 16) ^ ((k & 7) << 4)));
    }

    int lane = tid & 31, warp = tid >> 5;
    int wm = warp >> 2, wn = warp & 3;       // warp tile 64x32
    int quad = lane >> 2, qid = lane & 3;
    int l15 = lane & 15;
    uint32_t maskL = (uint32_t)((lane & 7) << 4);
    uint32_t rowA[4];
#pragma unroll
    for (int mt = 0; mt < 4; mt++)
        rowA[mt] = (uint32_t)((wm * 64 + mt * 16 + l15) * 128);
    uint32_t coff0 = (uint32_t)((lane >> 4) * 16);
    uint32_t bRow = (uint32_t)(l15 * 256);
    uint32_t bcol2[2];
#pragma unroll
    for (int np = 0; np < 2; np++)
        bcol2[np] = (uint32_t)(((uint32_t)(wn * 64 + (np * 2 + (lane >> 4)) * 16)) ^ maskL);

    float acc[4][4][4];
#pragma unroll
    for (int a = 0; a < 4; a++)
#pragma unroll
        for (int b = 0; b < 4; b++)
#pragma unroll
            for (int c = 0; c < 4; c++) acc[a][b][c] = 0.f;

    const int KT = KD / BK;

#pragma unroll
    for (int i = 0; i < 4; i++) cp16(aB[0] + aSo[i], aBase[i]);
#pragma unroll
    for (int j = 0; j < 4; j++) cp16(bB[0] + bSo[j], Bp + bGo[j]);
    cp_commit();

    for (int kt = 0; kt < KT; ++kt) {
        int buf = kt & 1;
        if (kt + 1 < KT) {
            int nb = buf ^ 1;
            uint32_t ka = (uint32_t)((kt + 1) * BK);
            size_t kb = (size_t)(kt + 1) * BK * ND;
#pragma unroll
            for (int i = 0; i < 4; i++) cp16(aB[nb] + aSo[i], aBase[i] + ka);
#pragma unroll
            for (int j = 0; j < 4; j++) cp16(bB[nb] + bSo[j], Bp + kb + bGo[j]);
            cp_commit();
            cp_wait<1>();
        } else {
            cp_wait<0>();
        }
        __syncthreads();

        // register-pipelined mainloop: bf one ks ahead
        uint32_t bfp[2][4][2];
#pragma unroll
        for (int np = 0; np < 2; np++) {
            uint32_t r[4];
            ldm_x4t(r, bB[buf] + bRow + bcol2[np]);
            bfp[0][2 * np][0]     = r[0]; bfp[0][2 * np][1]     = r[1];
            bfp[0][2 * np + 1][0] = r[2]; bfp[0][2 * np + 1][1] = r[3];
        }
#pragma unroll
        for (int ks = 0; ks < 4; ks++) {
            int cur = ks & 1;
            uint32_t kk2 = (uint32_t)(ks * 32);
            uint32_t af[4][4];
#pragma unroll
            for (int mt = 0; mt < 4; mt++)
                ldm_x4(af[mt], aB[buf] + rowA[mt] + ((kk2 + coff0) ^ maskL));
            if (ks < 3) {
#pragma unroll
                for (int np = 0; np < 2; np++) {
                    uint32_t r[4];
                    ldm_x4t(r, bB[buf] + bRow + (uint32_t)((ks + 1) * 4096) + bcol2[np]);
                    bfp[cur ^ 1][2 * np][0]     = r[0]; bfp[cur ^ 1][2 * np][1]     = r[1];
                    bfp[cur ^ 1][2 * np + 1][0] = r[2]; bfp[cur ^ 1][2 * np + 1][1] = r[3];
                }
            }
#pragma unroll
            for (int mt = 0; mt < 4; mt++)
#pragma unroll
                for (int nt = 0; nt < 4; nt++)
                    mma16816(acc[mt][nt], af[mt], bfp[cur][nt]);
        }
        __syncthreads();
    }

    __half* Ch = z ? u_buf : g_buf;
#pragma unroll
    for (int mt = 0; mt < 4; mt++) {
        int r0 = m0 + wm * 64 + mt * 16 + quad;
#pragma unroll
        for (int nt = 0; nt < 4; nt++) {
            int c = n0 + wn * 32 + nt * 8 + qid * 2;
            *(__half2*)&Ch[(size_t)r0 * ND + c] =
                __floats2half2_rn(acc[mt][nt][0], acc[mt][nt][1]);
            *(__half2*)&Ch[(size_t)(r0 + 8) * ND + c] =
                __floats2half2_rn(acc[mt][nt][2], acc[mt][nt][3]);
        }
    }
}

// Down GEMM: A = g_buf rows, B = dw_h, C -> d_buf. Grid n-fastest.
__global__ void __launch_bounds__(256, 2) moe_gemm_dn() {
    extern __shared__ char dsm[];
    const int KD = I_DIM, ND = H_DIM;

    int tid = threadIdx.x;
    int n0 = blockIdx.x * BN;
    int m0 = blockIdx.y * BM;
    if (m0 >= seg_off[E_NUM]) return;
    int e = 0;
    while (seg_off[e + 1] <= m0) ++e;

    uint32_t raw = smem_u32(dsm);
    uint32_t sbase = (raw + 1023u) & ~1023u;
    const uint32_t ASZ = BM * BK * 2;
    const uint32_t BSZ = BK * BN * 2;
    uint32_t aB[NSTG], bB[NSTG];
#pragma unroll
    for (int s = 0; s < NSTG; s++) {
        aB[s] = sbase + s * (ASZ + BSZ);
        bB[s] = sbase + s * (ASZ + BSZ) + ASZ;
    }

    const __half* Bp = dw_h + (size_t)e * KD * ND + n0;

    uint32_t aSo[4];
    const __half* aBase[4];
#pragma unroll
    for (int i = 0; i < 4; i++) {
        int idx = tid + i * 256;
        int r = idx >> 3, kg = idx & 7;
        aBase[i] = g_buf + (size_t)(m0 + r) * KD + kg * 8;
        aSo[i] = (uint32_t)(r * 128 + ((kg * 16) ^ ((r & 7) << 4)));
    }
    uint32_t bGo[4], bSo[4];
#pragma unroll
    for (int j = 0; j < 4; j++) {
        int idx = tid + j * 256;
        int k = idx >> 4, ng = idx & 15;
        bGo[j] = (uint32_t)(k * ND + ng * 8);
        bSo[j] = (uint32_t)(k * 256 + ((ng * 16) ^ ((k & 7) << 4)));
    }

    int lane = tid & 31, warp = tid >> 5;
    int wm = warp >> 2, wn = warp & 3;
    int quad = lane >> 2, qid = lane & 3;
    int l15 = lane & 15;
    uint32_t maskL = (uint32_t)((lane & 7) << 4);
    uint32_t rowA[4];
#pragma unroll
    for (int mt = 0; mt < 4; mt++)
        rowA[mt] = (uint32_t)((wm * 64 + mt * 16 + l15) * 128);
    uint32_t coff0 = (uint32_t)((lane >> 4) * 16);
    uint32_t bRow = (uint32_t)(l15 * 256);
    uint32_t bcol2[2];
#pragma unroll
    for (int np = 0; np < 2; np++)
        bcol2[np] = (uint32_t)(((uint32_t)(wn * 64 + (np * 2 + (lane >> 4)) * 16)) ^ maskL);

    float acc[4][4][4];
#pragma unroll
    for (int a = 0; a < 4; a++)
#pragma unroll
        for (int b = 0; b < 4; b++)
#pragma unroll
            for (int c = 0; c < 4; c++) acc[a][b][c] = 0.f;

    const int KT = KD / BK;

#pragma unroll
    for (int i = 0; i < 4; i++) cp16(aB[0] + aSo[i], aBase[i]);
#pragma unroll
    for (int j = 0; j < 4; j++) cp16(bB[0] + bSo[j], Bp + bGo[j]);
    cp_commit();

    for (int kt = 0; kt < KT; ++kt) {
        int buf = kt & 1;
        if (kt + 1 < KT) {
            int nb = buf ^ 1;
            uint32_t ka = (uint32_t)((kt + 1) * BK);
            size_t kb = (size_t)(kt + 1) * BK * ND;
#pragma unroll
            for (int i = 0; i < 4; i++) cp16(aB[nb] + aSo[i], aBase[i] + ka);
#pragma unroll
            for (int j = 0; j < 4; j++) cp16(bB[nb] + bSo[j], Bp + kb + bGo[j]);
            cp_commit();
            cp_wait<1>();
        } else {
            cp_wait<0>();
        }
        __syncthreads();

        uint32_t bfp[2][4][2];
#pragma unroll
        for (int np = 0; np < 2; np++) {
            uint32_t r[4];
            ldm_x4t(r, bB[buf] + bRow + bcol2[np]);
            bfp[0][2 * np][0]     = r[0]; bfp[0][2 * np][1]     = r[1];
            bfp[0][2 * np + 1][0] = r[2]; bfp[0][2 * np + 1][1] = r[3];
        }
#pragma unroll
        for (int ks = 0; ks < 4; ks++) {
            int cur = ks & 1;
            uint32_t kk2 = (uint32_t)(ks * 32);
            uint32_t af[4][4];
#pragma unroll
            for (int mt = 0; mt < 4; mt++)
                ldm_x4(af[mt], aB[buf] + rowA[mt] + ((kk2 + coff0) ^ maskL));
            if (ks < 3) {
#pragma unroll
                for (int np = 0; np < 2; np++) {
                    uint32_t r[4];
                    ldm_x4t(r, bB[buf] + bRow + (uint32_t)((ks + 1) * 4096) + bcol2[np]);
                    bfp[cur ^ 1][2 * np][0]     = r[0]; bfp[cur ^ 1][2 * np][1]     = r[1];
                    bfp[cur ^ 1][2 * np + 1][0] = r[2]; bfp[cur ^ 1][2 * np + 1][1] = r[3];
                }
            }
#pragma unroll
            for (int mt = 0; mt < 4; mt++)
#pragma unroll
                for (int nt = 0; nt < 4; nt++)
                    mma16816(acc[mt][nt], af[mt], bfp[cur][nt]);
        }
        __syncthreads();
    }

    // plain f32 stores into per-slot buffer (no atomics)
#pragma unroll
    for (int mt = 0; mt < 4; mt++) {
        int r0 = m0 + wm * 64 + mt * 16 + quad;
#pragma unroll
        for (int nt = 0; nt < 4; nt++) {
            int c = n0 + wn * 32 + nt * 8 + qid * 2;
            *(float2*)&d_buf[(size_t)r0 * ND + c] =
                make_float2(acc[mt][nt][0], acc[mt][nt][1]);
            *(float2*)&d_buf[(size_t)(r0 + 8) * ND + c] =
                make_float2(acc[mt][nt][2], acc[mt][nt][3]);
        }
    }
}

// ---------------- K6: swiglu * routing weight (in place into g_buf) ----------------
__global__ void swiglu_kernel() {
    size_t i8 = (size_t)blockIdx.x * blockDim.x + threadIdx.x;   // 8-half group index
    int row = (int)(i8 >> 9);                                     // I_DIM/8 = 512 groups/row
    if (row >= seg_off[E_NUM]) return;
    float w = pr_weight[row];
    __half2 g2[4], u2[4];
    *(uint4*)g2 = *(const uint4*)(g_buf + i8 * 8);
    *(uint4*)u2 = *(const uint4*)(u_buf + i8 * 8);
#pragma unroll
    for (int i = 0; i < 4; i++) {
        float2 g = __half22float2(g2[i]);
        float2 u = __half22float2(u2[i]);
        float hx = w * u.x * (g.x / (1.f + expf(-g.x)));
        float hy = w * u.y * (g.y / (1.f + expf(-g.y)));
        g2[i] = __floats2half2_rn(hx, hy);
    }
    *(uint4*)(g_buf + i8 * 8) = *(uint4*)g2;
}

// ---------------- K7: combine two slot rows per token -> out ----------------
__global__ void combine_kernel(float* __restrict__ out) {
    size_t idx = (size_t)blockIdx.x * blockDim.x + threadIdx.x;   // f4 index over T*H/4
    int t = (int)(idx >> 8);                                       // H/4 = 256
    int c4 = (int)(idx & 255);
    int s0 = slot_of[2 * t], s1 = slot_of[2 * t + 1];
    float4 a = ((const float4*)(d_buf + (size_t)s0 * H_DIM))[c4];
    float4 b = ((const float4*)(d_buf + (size_t)s1 * H_DIM))[c4];
    ((float4*)(out + (size_t)t * H_DIM))[c4] =
        make_float4(a.x + b.x, a.y + b.y, a.z + b.z, a.w + b.w);
}

// ---------------- launch ----------------
extern "C" void kernel_launch(void* const* d_in, const int* in_sizes, int n_in,
                              void* d_out, int out_size) {
    const float* hs  = (const float*)d_in[0];
    const float* gpw = (const float*)d_in[1];
    const float* gw  = (const float*)d_in[2];
    const float* uw  = (const float*)d_in[3];
    const float* dw  = (const float*)d_in[4];
    float* out = (float*)d_out;

    cudaFuncSetAttribute(moe_gemm_gu,
                         cudaFuncAttributeMaxDynamicSharedMemorySize, DSMEM_BYTES);
    cudaFuncSetAttribute(moe_gemm_dn,
                         cudaFuncAttributeMaxDynamicSharedMemorySize, DSMEM_BYTES);

    init_kernel<<<(CAP + 255) / 256, 256>>>();
    dim3 cw_grid((unsigned)((size_t)E_NUM * H_DIM * I_DIM / 8 / 256), 3);
    cvt_w_kernel<<<cw_grid, 256>>>(gw, uw, dw);
    router_kernel<<<T_TOK / 8, 256>>>(hs, gpw);   // also converts hs -> hs_h
    scatter_kernel<<<T_TOK / 256, 256>>>();       // computes seg_off in-block

    dim3 gu_grid(CAP / BM, I_DIM / BN, 2);   // m fastest: B slabs shared via L2
    moe_gemm_gu<<<gu_grid, 256, DSMEM_BYTES>>>();

    swiglu_kernel<<<(int)(((size_t)CAP * I_DIM / 8) / 256), 256>>>();

    dim3 dn_grid(H_DIM / BN, CAP / BM);      // n fastest: A slab read once from DRAM
    moe_gemm_dn<<<dn_grid, 256, DSMEM_BYTES>>>();

    combine_kernel<<<(int)(((size_t)T_TOK * H_DIM / 4) / 256), 256>>>(out);
}

// round 16
// speedup vs baseline: 1.0063x; 1.0063x over previous
#include <cuda_runtime.h>
#include <cuda_fp16.h>
#include <cstdint>
#include <math.h>

#define T_TOK 8192
#define H_DIM 1024
#define I_DIM 4096
#define E_NUM 8
#define TOPK  2
#define CAP   17408       // 16384 pairs + worst-case alignment padding, mult of 128
#define BM 128
#define BN 128
#define BK 64             // 64 halves = 128B rows for A tile
#define NSTG 2
#define DSMEM_BYTES (1024 + NSTG * (BM * BK * 2 + BK * BN * 2))   // ~65 KB -> 2 CTAs/SM

// ---------------- scratch (device globals: allocation-free) ----------------
__device__ __half hs_h[(size_t)T_TOK * H_DIM];
__device__ __half gw_h[(size_t)E_NUM * H_DIM * I_DIM];
__device__ __half uw_h[(size_t)E_NUM * H_DIM * I_DIM];
__device__ __half dw_h[(size_t)E_NUM * I_DIM * H_DIM];
__device__ __half g_buf[(size_t)CAP * I_DIM];   // gate acts -> swiglu result in place
__device__ __half u_buf[(size_t)CAP * I_DIM];   // up acts
__device__ float d_buf[(size_t)CAP * H_DIM];    // per-slot down results (pre-combine)
__device__ int   pr_token[CAP];
__device__ float pr_weight[CAP];
__device__ int   slot_of[T_TOK * TOPK];         // token,k -> compacted slot row
__device__ int   tok_e[T_TOK * TOPK];
__device__ float tok_w[T_TOK * TOPK];
__device__ int   e_count[E_NUM];
__device__ int   e_cursor[E_NUM];
__device__ int   seg_off[E_NUM + 1];

// ---------------- ptx helpers (family-portable: sm_80/90 era) ----------------
__device__ __forceinline__ uint32_t smem_u32(const void* p) {
    uint32_t a;
    asm("{ .reg .u64 t; cvta.to.shared.u64 t, %1; cvt.u32.u64 %0, t; }" : "=r"(a) : "l"(p));
    return a;
}
__device__ __forceinline__ void cp16(uint32_t s, const void* g) {
    asm volatile("cp.async.cg.shared.global [%0], [%1], 16;" :: "r"(s), "l"(g));
}
__device__ __forceinline__ void cp_commit() {
    asm volatile("cp.async.commit_group;" ::: "memory");
}
template <int N>
__device__ __forceinline__ void cp_wait() {
    asm volatile("cp.async.wait_group %0;" :: "n"(N) : "memory");
}
__device__ __forceinline__ void ldm_x4(uint32_t* r, uint32_t a) {
    asm volatile("ldmatrix.sync.aligned.m8n8.x4.shared.b16 {%0,%1,%2,%3},[%4];"
                 : "=r"(r[0]), "=r"(r[1]), "=r"(r[2]), "=r"(r[3]) : "r"(a));
}
__device__ __forceinline__ void ldm_x4t(uint32_t* r, uint32_t a) {
    asm volatile("ldmatrix.sync.aligned.m8n8.x4.trans.shared.b16 {%0,%1,%2,%3},[%4];"
                 : "=r"(r[0]), "=r"(r[1]), "=r"(r[2]), "=r"(r[3]) : "r"(a));
}
__device__ __forceinline__ void mma16816(float* c, const uint32_t* a, const uint32_t* b) {
    asm volatile(
        "mma.sync.aligned.m16n8k16.row.col.f32.f16.f16.f32 "
        "{%0,%1,%2,%3},{%4,%5,%6,%7},{%8,%9},{%0,%1,%2,%3};"
        : "+f"(c[0]), "+f"(c[1]), "+f"(c[2]), "+f"(c[3])
        : "r"(a[0]), "r"(a[1]), "r"(a[2]), "r"(a[3]), "r"(b[0]), "r"(b[1]));
}

// ---------------- f32 -> f16 weight conversion + control-state init ---------
// blockIdx.y selects tensor; y==0 blocks also zero the routing control state
// (blocks 0..67 cover all CAP slots; this kernel runs before router/scatter).
__global__ void cvt_w_kernel(const float* __restrict__ gw,
                             const float* __restrict__ uw,
                             const float* __restrict__ dw) {
    if (blockIdx.y == 0) {
        int gi = blockIdx.x * 256 + threadIdx.x;
        if (gi < E_NUM) { e_count[gi] = 0; e_cursor[gi] = 0; }
        if (gi < CAP)   { pr_token[gi] = 0; pr_weight[gi] = 0.f; }
    }
    size_t i = ((size_t)blockIdx.x * blockDim.x + threadIdx.x) * 8;
    const float* src = (blockIdx.y == 0) ? gw : (blockIdx.y == 1) ? uw : dw;
    __half* dst = (blockIdx.y == 0) ? gw_h : (blockIdx.y == 1) ? uw_h : dw_h;
    float4 a = *(const float4*)(src + i);
    float4 b = *(const float4*)(src + i + 4);
    __half2 h[4] = { __floats2half2_rn(a.x, a.y), __floats2half2_rn(a.z, a.w),
                     __floats2half2_rn(b.x, b.y), __floats2half2_rn(b.z, b.w) };
    *(uint4*)(dst + i) = *(uint4*)h;
}

// ---------------- K1: router (1 warp per token, float4 loads) ---------------
// Side effect: converts hs -> hs_h (this kernel already streams all of hs).
__global__ void router_kernel(const float* __restrict__ hs,
                              const float* __restrict__ gpw) {
    __shared__ int s_cnt[E_NUM];
    int tid = threadIdx.x, warp = tid >> 5, lane = tid & 31;
    if (tid < E_NUM) s_cnt[tid] = 0;
    __syncthreads();

    int t = blockIdx.x * 8 + warp;
    const float* x = hs + (size_t)t * H_DIM;
    float acc[E_NUM];
#pragma unroll
    for (int e = 0; e < E_NUM; e++) acc[e] = 0.f;

#pragma unroll
    for (int it = 0; it < H_DIM / 128; it++) {          // 8 iters, 128 floats/warp/iter
        int kk = it * 128 + lane * 4;
        float4 xv = *(const float4*)(x + kk);
        __half2 h01 = __floats2half2_rn(xv.x, xv.y);
        __half2 h23 = __floats2half2_rn(xv.z, xv.w);
        uint2 hpk = make_uint2(*(uint32_t*)&h01, *(uint32_t*)&h23);
        *(uint2*)&hs_h[(size_t)t * H_DIM + kk] = hpk;
#pragma unroll
        for (int e = 0; e < E_NUM; e++) {
            float4 wv = *(const float4*)(gpw + e * H_DIM + kk);
            acc[e] = fmaf(xv.x, wv.x, acc[e]);
            acc[e] = fmaf(xv.y, wv.y, acc[e]);
            acc[e] = fmaf(xv.z, wv.z, acc[e]);
            acc[e] = fmaf(xv.w, wv.w, acc[e]);
        }
    }
#pragma unroll
    for (int e = 0; e < E_NUM; e++)
#pragma unroll
        for (int off = 16; off > 0; off >>= 1)
            acc[e] += __shfl_xor_sync(0xFFFFFFFFu, acc[e], off);

    if (lane == 0) {
        float m = acc[0];
#pragma unroll
        for (int e = 1; e < E_NUM; e++) m = fmaxf(m, acc[e]);
        int i0 = 0;
#pragma unroll
        for (int e = 1; e < E_NUM; e++) if (acc[e] > acc[i0]) i0 = e;
        int i1 = (i0 == 0) ? 1 : 0;
#pragma unroll
        for (int e = 0; e < E_NUM; e++)
            if (e != i0 && acc[e] > acc[i1]) i1 = e;
        float p0 = expf(acc[i0] - m);
        float p1 = expf(acc[i1] - m);
        float inv = 1.f / (p0 + p1);
        tok_e[2 * t]     = i0; tok_w[2 * t]     = p0 * inv;
        tok_e[2 * t + 1] = i1; tok_w[2 * t + 1] = p1 * inv;
        atomicAdd(&s_cnt[i0], 1);
        atomicAdd(&s_cnt[i1], 1);
    }
    __syncthreads();
    if (tid < E_NUM) atomicAdd(&e_count[tid], s_cnt[tid]);
}

// ---------------- K3: scatter (computes 128-aligned seg offsets in-block) ----
__global__ void scatter_kernel() {
    __shared__ int cnt[E_NUM];
    __shared__ int base[E_NUM];
    __shared__ int seg[E_NUM + 1];
    int tid = threadIdx.x;
    if (tid < E_NUM) cnt[tid] = 0;
    if (tid == 0) {
        int off = 0;
        for (int e = 0; e < E_NUM; e++) {
            seg[e] = off;
            off += (e_count[e] + BM - 1) & ~(BM - 1);
        }
        seg[E_NUM] = off;
        if (blockIdx.x == 0)
            for (int e = 0; e <= E_NUM; e++) seg_off[e] = seg[e];
    }
    __syncthreads();

    int t = blockIdx.x * 256 + tid;
    int e0 = tok_e[2 * t], e1 = tok_e[2 * t + 1];
    int r0 = atomicAdd(&cnt[e0], 1);
    int r1 = atomicAdd(&cnt[e1], 1);
    __syncthreads();
    if (tid < E_NUM) base[tid] = atomicAdd(&e_cursor[tid], cnt[tid]);
    __syncthreads();

    int p0 = seg[e0] + base[e0] + r0;
    pr_token[p0] = t; pr_weight[p0] = tok_w[2 * t];
    slot_of[2 * t] = p0;
    int p1 = seg[e1] + base[e1] + r1;
    pr_token[p1] = t; pr_weight[p1] = tok_w[2 * t + 1];
    slot_of[2 * t + 1] = p1;
}

// ---------------- grouped fp16 GEMM, BM=128/BN=128, 2 CTAs/SM (R14 core) ----
// B fragments loaded with ldmatrix.x4.trans: 2 LDSM per ks instead of 4.
// GU: gate+up in one launch, z in {0,1} selects weight/dest. Grid m-fastest.
__global__ void __launch_bounds__(256, 2) moe_gemm_gu() {
    extern __shared__ char dsm[];
    const int KD = H_DIM, ND = I_DIM;

    int tid = threadIdx.x;
    int m0 = blockIdx.x * BM;
    int n0 = blockIdx.y * BN;
    int z  = blockIdx.z;               // 0 = gate, 1 = up
    if (m0 >= seg_off[E_NUM]) return;
    int e = 0;
    while (seg_off[e + 1] <= m0) ++e;

    uint32_t raw = smem_u32(dsm);
    uint32_t sbase = (raw + 1023u) & ~1023u;
    const uint32_t ASZ = BM * BK * 2;        // 16 KB
    const uint32_t BSZ = BK * BN * 2;        // 16 KB
    uint32_t aB[NSTG], bB[NSTG];
#pragma unroll
    for (int s = 0; s < NSTG; s++) {
        aB[s] = sbase + s * (ASZ + BSZ);
        bB[s] = sbase + s * (ASZ + BSZ) + ASZ;
    }

    const __half* Bw = z ? uw_h : gw_h;
    const __half* Bp = Bw + (size_t)e * KD * ND + n0;

    uint32_t aSo[4];
    const __half* aBase[4];
#pragma unroll
    for (int i = 0; i < 4; i++) {
        int idx = tid + i * 256;
        int r = idx >> 3, kg = idx & 7;
        int arow = pr_token[m0 + r];
        aBase[i] = hs_h + (size_t)arow * KD + kg * 8;
        aSo[i] = (uint32_t)(r * 128 + ((kg * 16) ^ ((r & 7) << 4)));
    }
    uint32_t bGo[4], bSo[4];
#pragma unroll
    for (int j = 0; j < 4; j++) {
        int idx = tid + j * 256;
        int k = idx >> 4, ng = idx & 15;
        bGo[j] = (uint32_t)(k * ND + ng * 8);
        bSo[j] = (uint32_t)(k * 256 + ((ng * 16) ^ ((k & 7) << 4)));
    }

    int lane = tid & 31, warp = tid >> 5;
    int wm = warp >> 2, wn = warp & 3;       // warp tile 64x32
    int quad = lane >> 2, qid = lane & 3;
    int l15 = lane & 15;
    uint32_t maskL = (uint32_t)((lane & 7) << 4);
    uint32_t rowA[4];
#pragma unroll
    for (int mt = 0; mt < 4; mt++)
        rowA[mt] = (uint32_t)((wm * 64 + mt * 16 + l15) * 128);
    uint32_t coff0 = (uint32_t)((lane >> 4) * 16);
    uint32_t bRow = (uint32_t)(l15 * 256);
    // x4.trans column blocks: lanes<16 -> nt=2np, lanes>=16 -> nt=2np+1
    uint32_t bcol2[2];
#pragma unroll
    for (int np = 0; np < 2; np++)
        bcol2[np] = (uint32_t)(((uint32_t)(wn * 64 + (np * 2 + (lane >> 4)) * 16)) ^ maskL);

    float acc[4][4][4];
#pragma unroll
    for (int a = 0; a < 4; a++)
#pragma unroll
        for (int b = 0; b < 4; b++)
#pragma unroll
            for (int c = 0; c < 4; c++) acc[a][b][c] = 0.f;

    const int KT = KD / BK;

#pragma unroll
    for (int i = 0; i < 4; i++) cp16(aB[0] + aSo[i], aBase[i]);
#pragma unroll
    for (int j = 0; j < 4; j++) cp16(bB[0] + bSo[j], Bp + bGo[j]);
    cp_commit();

    for (int kt = 0; kt < KT; ++kt) {
        int buf = kt & 1;
        if (kt + 1 < KT) {
            int nb = buf ^ 1;
            uint32_t ka = (uint32_t)((kt + 1) * BK);
            size_t kb = (size_t)(kt + 1) * BK * ND;
#pragma unroll
            for (int i = 0; i < 4; i++) cp16(aB[nb] + aSo[i], aBase[i] + ka);
#pragma unroll
            for (int j = 0; j < 4; j++) cp16(bB[nb] + bSo[j], Bp + kb + bGo[j]);
            cp_commit();
            cp_wait<1>();
        } else {
            cp_wait<0>();
        }
        __syncthreads();

#pragma unroll
        for (int ks = 0; ks < 4; ks++) {
            uint32_t kk2 = (uint32_t)(ks * 32);
            uint32_t af[4][4];
#pragma unroll
            for (int mt = 0; mt < 4; mt++)
                ldm_x4(af[mt], aB[buf] + rowA[mt] + ((kk2 + coff0) ^ maskL));
            uint32_t bf[4][2];
#pragma unroll
            for (int np = 0; np < 2; np++) {
                uint32_t r[4];
                ldm_x4t(r, bB[buf] + bRow + (uint32_t)(ks * 4096) + bcol2[np]);
                bf[2 * np][0]     = r[0]; bf[2 * np][1]     = r[1];
                bf[2 * np + 1][0] = r[2]; bf[2 * np + 1][1] = r[3];
            }
#pragma unroll
            for (int mt = 0; mt < 4; mt++)
#pragma unroll
                for (int nt = 0; nt < 4; nt++)
                    mma16816(acc[mt][nt], af[mt], bf[nt]);
        }
        __syncthreads();
    }

    __half* Ch = z ? u_buf : g_buf;
#pragma unroll
    for (int mt = 0; mt < 4; mt++) {
        int r0 = m0 + wm * 64 + mt * 16 + quad;
#pragma unroll
        for (int nt = 0; nt < 4; nt++) {
            int c = n0 + wn * 32 + nt * 8 + qid * 2;
            *(__half2*)&Ch[(size_t)r0 * ND + c] =
                __floats2half2_rn(acc[mt][nt][0], acc[mt][nt][1]);
            *(__half2*)&Ch[(size_t)(r0 + 8) * ND + c] =
                __floats2half2_rn(acc[mt][nt][2], acc[mt][nt][3]);
        }
    }
}

// Down GEMM: A = g_buf rows, B = dw_h, C -> d_buf. Grid n-fastest.
__global__ void __launch_bounds__(256, 2) moe_gemm_dn() {
    extern __shared__ char dsm[];
    const int KD = I_DIM, ND = H_DIM;

    int tid = threadIdx.x;
    int n0 = blockIdx.x * BN;
    int m0 = blockIdx.y * BM;
    if (m0 >= seg_off[E_NUM]) return;
    int e = 0;
    while (seg_off[e + 1] <= m0) ++e;

    uint32_t raw = smem_u32(dsm);
    uint32_t sbase = (raw + 1023u) & ~1023u;
    const uint32_t ASZ = BM * BK * 2;
    const uint32_t BSZ = BK * BN * 2;
    uint32_t aB[NSTG], bB[NSTG];
#pragma unroll
    for (int s = 0; s < NSTG; s++) {
        aB[s] = sbase + s * (ASZ + BSZ);
        bB[s] = sbase + s * (ASZ + BSZ) + ASZ;
    }

    const __half* Bp = dw_h + (size_t)e * KD * ND + n0;

    uint32_t aSo[4];
    const __half* aBase[4];
#pragma unroll
    for (int i = 0; i < 4; i++) {
        int idx = tid + i * 256;
        int r = idx >> 3, kg = idx & 7;
        aBase[i] = g_buf + (size_t)(m0 + r) * KD + kg * 8;
        aSo[i] = (uint32_t)(r * 128 + ((kg * 16) ^ ((r & 7) << 4)));
    }
    uint32_t bGo[4], bSo[4];
#pragma unroll
    for (int j = 0; j < 4; j++) {
        int idx = tid + j * 256;
        int k = idx >> 4, ng = idx & 15;
        bGo[j] = (uint32_t)(k * ND + ng * 8);
        bSo[j] = (uint32_t)(k * 256 + ((ng * 16) ^ ((k & 7) << 4)));
    }

    int lane = tid & 31, warp = tid >> 5;
    int wm = warp >> 2, wn = warp & 3;
    int quad = lane >> 2, qid = lane & 3;
    int l15 = lane & 15;
    uint32_t maskL = (uint32_t)((lane & 7) << 4);
    uint32_t rowA[4];
#pragma unroll
    for (int mt = 0; mt < 4; mt++)
        rowA[mt] = (uint32_t)((wm * 64 + mt * 16 + l15) * 128);
    uint32_t coff0 = (uint32_t)((lane >> 4) * 16);
    uint32_t bRow = (uint32_t)(l15 * 256);
    uint32_t bcol2[2];
#pragma unroll
    for (int np = 0; np < 2; np++)
        bcol2[np] = (uint32_t)(((uint32_t)(wn * 64 + (np * 2 + (lane >> 4)) * 16)) ^ maskL);

    float acc[4][4][4];
#pragma unroll
    for (int a = 0; a < 4; a++)
#pragma unroll
        for (int b = 0; b < 4; b++)
#pragma unroll
            for (int c = 0; c < 4; c++) acc[a][b][c] = 0.f;

    const int KT = KD / BK;

#pragma unroll
    for (int i = 0; i < 4; i++) cp16(aB[0] + aSo[i], aBase[i]);
#pragma unroll
    for (int j = 0; j < 4; j++) cp16(bB[0] + bSo[j], Bp + bGo[j]);
    cp_commit();

    for (int kt = 0; kt < KT; ++kt) {
        int buf = kt & 1;
        if (kt + 1 < KT) {
            int nb = buf ^ 1;
            uint32_t ka = (uint32_t)((kt + 1) * BK);
            size_t kb = (size_t)(kt + 1) * BK * ND;
#pragma unroll
            for (int i = 0; i < 4; i++) cp16(aB[nb] + aSo[i], aBase[i] + ka);
#pragma unroll
            for (int j = 0; j < 4; j++) cp16(bB[nb] + bSo[j], Bp + kb + bGo[j]);
            cp_commit();
            cp_wait<1>();
        } else {
            cp_wait<0>();
        }
        __syncthreads();

#pragma unroll
        for (int ks = 0; ks < 4; ks++) {
            uint32_t kk2 = (uint32_t)(ks * 32);
            uint32_t af[4][4];
#pragma unroll
            for (int mt = 0; mt < 4; mt++)
                ldm_x4(af[mt], aB[buf] + rowA[mt] + ((kk2 + coff0) ^ maskL));
            uint32_t bf[4][2];
#pragma unroll
            for (int np = 0; np < 2; np++) {
                uint32_t r[4];
                ldm_x4t(r, bB[buf] + bRow + (uint32_t)(ks * 4096) + bcol2[np]);
                bf[2 * np][0]     = r[0]; bf[2 * np][1]     = r[1];
                bf[2 * np + 1][0] = r[2]; bf[2 * np + 1][1] = r[3];
            }
#pragma unroll
            for (int mt = 0; mt < 4; mt++)
#pragma unroll
                for (int nt = 0; nt < 4; nt++)
                    mma16816(acc[mt][nt], af[mt], bf[nt]);
        }
        __syncthreads();
    }

    // plain f32 stores into per-slot buffer (no atomics)
#pragma unroll
    for (int mt = 0; mt < 4; mt++) {
        int r0 = m0 + wm * 64 + mt * 16 + quad;
#pragma unroll
        for (int nt = 0; nt < 4; nt++) {
            int c = n0 + wn * 32 + nt * 8 + qid * 2;
            *(float2*)&d_buf[(size_t)r0 * ND + c] =
                make_float2(acc[mt][nt][0], acc[mt][nt][1]);
            *(float2*)&d_buf[(size_t)(r0 + 8) * ND + c] =
                make_float2(acc[mt][nt][2], acc[mt][nt][3]);
        }
    }
}

// ---------------- K6: swiglu * routing weight (in place into g_buf) ----------------
__global__ void swiglu_kernel() {
    size_t i8 = (size_t)blockIdx.x * blockDim.x + threadIdx.x;   // 8-half group index
    int row = (int)(i8 >> 9);                                     // I_DIM/8 = 512 groups/row
    if (row >= seg_off[E_NUM]) return;
    float w = pr_weight[row];
    __half2 g2[4], u2[4];
    *(uint4*)g2 = *(const uint4*)(g_buf + i8 * 8);
    *(uint4*)u2 = *(const uint4*)(u_buf + i8 * 8);
#pragma unroll
    for (int i = 0; i < 4; i++) {
        float2 g = __half22float2(g2[i]);
        float2 u = __half22float2(u2[i]);
        float hx = w * u.x * (g.x / (1.f + expf(-g.x)));
        float hy = w * u.y * (g.y / (1.f + expf(-g.y)));
        g2[i] = __floats2half2_rn(hx, hy);
    }
    *(uint4*)(g_buf + i8 * 8) = *(uint4*)g2;
}

// ---------------- K7: combine two slot rows per token -> out ----------------
__global__ void combine_kernel(float* __restrict__ out) {
    size_t idx = (size_t)blockIdx.x * blockDim.x + threadIdx.x;   // f4 index over T*H/4
    int t = (int)(idx >> 8);                                       // H/4 = 256
    int c4 = (int)(idx & 255);
    int s0 = slot_of[2 * t], s1 = slot_of[2 * t + 1];
    float4 a = ((const float4*)(d_buf + (size_t)s0 * H_DIM))[c4];
    float4 b = ((const float4*)(d_buf + (size_t)s1 * H_DIM))[c4];
    ((float4*)(out + (size_t)t * H_DIM))[c4] =
        make_float4(a.x + b.x, a.y + b.y, a.z + b.z, a.w + b.w);
}

// ---------------- launch ----------------
extern "C" void kernel_launch(void* const* d_in, const int* in_sizes, int n_in,
                              void* d_out, int out_size) {
    const float* hs  = (const float*)d_in[0];
    const float* gpw = (const float*)d_in[1];
    const float* gw  = (const float*)d_in[2];
    const float* uw  = (const float*)d_in[3];
    const float* dw  = (const float*)d_in[4];
    float* out = (float*)d_out;

    cudaFuncSetAttribute(moe_gemm_gu,
                         cudaFuncAttributeMaxDynamicSharedMemorySize, DSMEM_BYTES);
    cudaFuncSetAttribute(moe_gemm_dn,
                         cudaFuncAttributeMaxDynamicSharedMemorySize, DSMEM_BYTES);

    dim3 cw_grid((unsigned)((size_t)E_NUM * H_DIM * I_DIM / 8 / 256), 3);
    cvt_w_kernel<<<cw_grid, 256>>>(gw, uw, dw);    // also zeroes control state
    router_kernel<<<T_TOK / 8, 256>>>(hs, gpw);    // also converts hs -> hs_h
    scatter_kernel<<<T_TOK / 256, 256>>>();        // computes seg_off in-block

    dim3 gu_grid(CAP / BM, I_DIM / BN, 2);   // m fastest: B slabs shared via L2
    moe_gemm_gu<<<gu_grid, 256, DSMEM_BYTES>>>();

    swiglu_kernel<<<(int)(((size_t)CAP * I_DIM / 8) / 256), 256>>>();

    dim3 dn_grid(H_DIM / BN, CAP / BM);      // n fastest: A slab read once from DRAM
    moe_gemm_dn<<<dn_grid, 256, DSMEM_BYTES>>>();

    combine_kernel<<<(int)(((size_t)T_TOK * H_DIM / 4) / 256), 256>>>(out);
}